// round 6
// baseline (speedup 1.0000x reference)
#include <cuda_runtime.h>
#include <cstdint>

#define NN_MAX 50000
#define EE_MAX 400000

// ---------------- scratch (device globals; no allocs allowed) ----------------
__device__ float g_Wcomb[128 * 512];      // [k][j]: Wn | Wq@A1q | Wk@A1k | Wv
__device__ float g_bc[512];               // bn | 0 | 0 | bv
__device__ float g_Me[64 * 128];          // We@A1e
__device__ float g_c1[128];               // bq@A1q + bk@A1k + be@A1e + b1
__device__ float g_H[NN_MAX * 128];
__device__ float g_Q[NN_MAX * 128];
__device__ float g_Kf[NN_MAX * 128];
__device__ float g_V[NN_MAX * 128];
__device__ float g_s[EE_MAX];
__device__ float g_pmax[512];
__device__ float g_psum[512];
__device__ float g_red[2];                // gmax, 1/gsum
__device__ float g_acc[NN_MAX * 128];

__device__ __forceinline__ float lrelu(float x) { return x > 0.f ? x : 0.2f * x; }

__device__ __forceinline__ uint32_t f2tf32(float x) {
    uint32_t r; asm("cvt.rna.tf32.f32 %0, %1;" : "=r"(r) : "f"(x)); return r;
}

__device__ __forceinline__ void mma_tf32(float c[4], const uint32_t a[4],
                                         uint32_t b0, uint32_t b1) {
    asm volatile(
        "mma.sync.aligned.m16n8k8.row.col.f32.tf32.tf32.f32 "
        "{%0,%1,%2,%3}, {%4,%5,%6,%7}, {%8,%9}, {%0,%1,%2,%3};"
        : "+f"(c[0]), "+f"(c[1]), "+f"(c[2]), "+f"(c[3])
        : "r"(a[0]), "r"(a[1]), "r"(a[2]), "r"(a[3]), "r"(b0), "r"(b1));
}

// ---------------- prep: fold weights ----------------
__global__ void prep_kernel(const float* __restrict__ Wn, const float* __restrict__ Wq,
                            const float* __restrict__ Wk, const float* __restrict__ Wv,
                            const float* __restrict__ We, const float* __restrict__ A1,
                            const float* __restrict__ b1, const float* __restrict__ bq,
                            const float* __restrict__ bk, const float* __restrict__ be,
                            const float* __restrict__ bn, const float* __restrict__ bv) {
    int t = blockIdx.x * 256 + threadIdx.x;
    if (t < 128 * 512) {
        int k = t >> 9, j = t & 511;
        float val;
        if (j < 128) {
            val = Wn[k * 128 + j];
        } else if (j < 256) {
            int jj = j - 128; float s = 0.f;
            #pragma unroll 8
            for (int u = 0; u < 128; u++) s += Wq[k * 128 + u] * A1[u * 128 + jj];
            val = s;
        } else if (j < 384) {
            int jj = j - 256; float s = 0.f;
            #pragma unroll 8
            for (int u = 0; u < 128; u++) s += Wk[k * 128 + u] * A1[(128 + u) * 128 + jj];
            val = s;
        } else {
            val = Wv[k * 128 + (j - 384)];
        }
        g_Wcomb[t] = val;
    } else if (t < 65536 + 64 * 128) {
        int i = t - 65536;
        int k = i >> 7, j = i & 127;
        float s = 0.f;
        #pragma unroll 8
        for (int u = 0; u < 128; u++) s += We[k * 128 + u] * A1[(256 + u) * 128 + j];
        g_Me[i] = s;
    } else if (t < 65536 + 8192 + 128) {
        int j = t - 65536 - 8192;
        float s = b1[j];
        for (int u = 0; u < 128; u++) {
            s += bq[u] * A1[u * 128 + j];
            s += bk[u] * A1[(128 + u) * 128 + j];
            s += be[u] * A1[(256 + u) * 128 + j];
        }
        g_c1[j] = s;
    } else if (t < 65536 + 8192 + 128 + 512) {
        int j = t - (65536 + 8192 + 128);
        g_bc[j] = (j < 128) ? bn[j] : (j >= 384 ? bv[j - 384] : 0.f);
    }
}

// ---------------- node GEMM: C[M,512] = A[M,128] @ g_Wcomb + g_bc ----------------
__global__ void __launch_bounds__(256) node_gemm_kernel(const float* __restrict__ A, int M) {
    __shared__ float sA[64 * 36];
    __shared__ float sB[32 * 128];

    int tid = threadIdx.x;
    int tx = tid & 15, ty = tid >> 4;
    int rowBase = blockIdx.y * 64;
    int colBase = blockIdx.x * 128;

    float acc[4][8];
    #pragma unroll
    for (int i = 0; i < 4; i++)
        #pragma unroll
        for (int j = 0; j < 8; j++) acc[i][j] = 0.f;

    #pragma unroll
    for (int k0 = 0; k0 < 128; k0 += 32) {
        #pragma unroll
        for (int i = 0; i < 2; i++) {
            int s = tid + i * 256;
            int r = s >> 3, c4 = s & 7;
            int row = rowBase + r;
            float4 v = make_float4(0.f, 0.f, 0.f, 0.f);
            if (row < M) v = *reinterpret_cast<const float4*>(&A[row * 128 + k0 + c4 * 4]);
            *reinterpret_cast<float4*>(&sA[r * 36 + c4 * 4]) = v;
        }
        #pragma unroll
        for (int i = 0; i < 4; i++) {
            int s = tid + i * 256;
            int r = s >> 5, c4 = s & 31;
            *reinterpret_cast<float4*>(&sB[r * 128 + c4 * 4]) =
                *reinterpret_cast<const float4*>(&g_Wcomb[(k0 + r) * 512 + colBase + c4 * 4]);
        }
        __syncthreads();
        #pragma unroll
        for (int k = 0; k < 32; k++) {
            float a[4];
            #pragma unroll
            for (int i = 0; i < 4; i++) a[i] = sA[(ty * 4 + i) * 36 + k];
            float4 b0 = *reinterpret_cast<const float4*>(&sB[k * 128 + tx * 4]);
            float4 b1 = *reinterpret_cast<const float4*>(&sB[k * 128 + 64 + tx * 4]);
            #pragma unroll
            for (int i = 0; i < 4; i++) {
                acc[i][0] += a[i] * b0.x; acc[i][1] += a[i] * b0.y;
                acc[i][2] += a[i] * b0.z; acc[i][3] += a[i] * b0.w;
                acc[i][4] += a[i] * b1.x; acc[i][5] += a[i] * b1.y;
                acc[i][6] += a[i] * b1.z; acc[i][7] += a[i] * b1.w;
            }
        }
        __syncthreads();
    }

    int grp = colBase >> 7;
    float* C = (grp == 0) ? g_H : (grp == 1) ? g_Q : (grp == 2) ? g_Kf : g_V;
    float4 bias0 = *reinterpret_cast<const float4*>(&g_bc[colBase + tx * 4]);
    float4 bias1 = *reinterpret_cast<const float4*>(&g_bc[colBase + 64 + tx * 4]);
    #pragma unroll
    for (int i = 0; i < 4; i++) {
        int row = rowBase + ty * 4 + i;
        if (row < M) {
            float4 o0 = make_float4(acc[i][0] + bias0.x, acc[i][1] + bias0.y,
                                    acc[i][2] + bias0.z, acc[i][3] + bias0.w);
            float4 o1 = make_float4(acc[i][4] + bias1.x, acc[i][5] + bias1.y,
                                    acc[i][6] + bias1.z, acc[i][7] + bias1.w);
            *reinterpret_cast<float4*>(&C[row * 128 + tx * 4])      = o0;
            *reinterpret_cast<float4*>(&C[row * 128 + 64 + tx * 4]) = o1;
        }
    }
}

// ---------------- fused edge kernel (tf32 tensor-core mainloop) ----------------
// per block: 64 edges. GEMM: EF[64,64] @ Me[64,128] via mma.sync m16n8k8 tf32,
// hi/lo compensated (3 MMAs) -> fp32-accurate. Accs staged through smem,
// then epilogue: hm = lrelu(acc + Xq[src] + Xk[tgt] + c1), heads via A2,
// shfl-reduce -> s[e].
//
// dynamic smem layout (float indices):
//   A_HI = 0      : EF hi, [64][68]  (4352 floats)
//   A_LO = 4352   : EF lo, [64][68]
//   B_HI = 8704   : Me hi, [64][136] (8704 floats)
//   B_LO = 17408  : Me lo, [64][136]
//   A2   = 26112  : 1024 floats
//   B2   = 27136  : 8 floats
// total 27144 floats = 108576 bytes.  s_acc (epilogue) reuses A region, [64][132].
#define EDGE_SMEM_FLOATS 27144
#define EDGE_SMEM_BYTES  (EDGE_SMEM_FLOATS * 4)
#define OFF_ALO 4352
#define OFF_BHI 8704
#define OFF_BLO 17408
#define OFF_A2  26112
#define OFF_B2  27136

__global__ void __launch_bounds__(256) edge_fused_kernel(
    const float* __restrict__ EF, const int* __restrict__ EI, int E,
    const float* __restrict__ A2, const float* __restrict__ b2) {
    extern __shared__ float smem[];

    int tid = threadIdx.x;
    int e0 = blockIdx.x * 64;

    // ---- load phase: EF -> hi/lo tf32, Me -> hi/lo tf32, A2, b2 ----
    for (int i = tid; i < 1024; i += 256) smem[OFF_A2 + i] = A2[i];
    if (tid < 8) smem[OFF_B2 + tid] = b2[tid];

    #pragma unroll
    for (int i = 0; i < 4; i++) {                       // EF: 64x64 = 1024 float4
        int s = tid + i * 256;
        int r = s >> 4, c4 = s & 15;
        int e = e0 + r;
        float4 v = make_float4(0.f, 0.f, 0.f, 0.f);
        if (e < E) v = *reinterpret_cast<const float4*>(&EF[e * 64 + c4 * 4]);
        float4 hi, lo;
        hi.x = __uint_as_float(f2tf32(v.x)); lo.x = __uint_as_float(f2tf32(v.x - hi.x));
        hi.y = __uint_as_float(f2tf32(v.y)); lo.y = __uint_as_float(f2tf32(v.y - hi.y));
        hi.z = __uint_as_float(f2tf32(v.z)); lo.z = __uint_as_float(f2tf32(v.z - hi.z));
        hi.w = __uint_as_float(f2tf32(v.w)); lo.w = __uint_as_float(f2tf32(v.w - hi.w));
        *reinterpret_cast<float4*>(&smem[r * 68 + c4 * 4])           = hi;
        *reinterpret_cast<float4*>(&smem[OFF_ALO + r * 68 + c4 * 4]) = lo;
    }
    #pragma unroll
    for (int i = 0; i < 8; i++) {                       // Me: 64x128 = 2048 float4
        int s = tid + i * 256;
        int r = s >> 5, c4 = s & 31;
        float4 v = *reinterpret_cast<const float4*>(&g_Me[r * 128 + c4 * 4]);
        float4 hi, lo;
        hi.x = __uint_as_float(f2tf32(v.x)); lo.x = __uint_as_float(f2tf32(v.x - hi.x));
        hi.y = __uint_as_float(f2tf32(v.y)); lo.y = __uint_as_float(f2tf32(v.y - hi.y));
        hi.z = __uint_as_float(f2tf32(v.z)); lo.z = __uint_as_float(f2tf32(v.z - hi.z));
        hi.w = __uint_as_float(f2tf32(v.w)); lo.w = __uint_as_float(f2tf32(v.w - hi.w));
        *reinterpret_cast<float4*>(&smem[OFF_BHI + r * 136 + c4 * 4]) = hi;
        *reinterpret_cast<float4*>(&smem[OFF_BLO + r * 136 + c4 * 4]) = lo;
    }
    __syncthreads();

    // ---- MMA phase: each warp owns 16 edges x 64 cols ----
    int w = tid >> 5, lane = tid & 31;
    int m0 = (w & 3) * 16;
    int n0 = (w >> 2) * 64;
    int g = lane >> 2, t4 = lane & 3;

    float c[8][4];
    #pragma unroll
    for (int nt = 0; nt < 8; nt++)
        #pragma unroll
        for (int j = 0; j < 4; j++) c[nt][j] = 0.f;

    #pragma unroll
    for (int kt = 0; kt < 8; kt++) {
        int ab = (m0 + g) * 68 + kt * 8 + t4;
        uint32_t ahi[4], alo[4];
        ahi[0] = __float_as_uint(smem[ab]);
        ahi[1] = __float_as_uint(smem[ab + 8 * 68]);
        ahi[2] = __float_as_uint(smem[ab + 4]);
        ahi[3] = __float_as_uint(smem[ab + 8 * 68 + 4]);
        alo[0] = __float_as_uint(smem[OFF_ALO + ab]);
        alo[1] = __float_as_uint(smem[OFF_ALO + ab + 8 * 68]);
        alo[2] = __float_as_uint(smem[OFF_ALO + ab + 4]);
        alo[3] = __float_as_uint(smem[OFF_ALO + ab + 8 * 68 + 4]);
        #pragma unroll
        for (int nt = 0; nt < 8; nt++) {
            int bb = (kt * 8 + t4) * 136 + n0 + nt * 8 + g;
            uint32_t bhi0 = __float_as_uint(smem[OFF_BHI + bb]);
            uint32_t bhi1 = __float_as_uint(smem[OFF_BHI + bb + 4 * 136]);
            uint32_t blo0 = __float_as_uint(smem[OFF_BLO + bb]);
            uint32_t blo1 = __float_as_uint(smem[OFF_BLO + bb + 4 * 136]);
            mma_tf32(c[nt], ahi, bhi0, bhi1);
            mma_tf32(c[nt], alo, bhi0, bhi1);
            mma_tf32(c[nt], ahi, blo0, blo1);
        }
    }
    __syncthreads();     // everyone done reading A region

    // ---- stage accs into smem: s_acc[edge][col], stride 132 (reuses A region) ----
    #pragma unroll
    for (int nt = 0; nt < 8; nt++) {
        int col = n0 + nt * 8 + t4 * 2;
        *reinterpret_cast<float2*>(&smem[(m0 + g) * 132 + col]) =
            make_float2(c[nt][0], c[nt][1]);
        *reinterpret_cast<float2*>(&smem[(m0 + g + 8) * 132 + col]) =
            make_float2(c[nt][2], c[nt][3]);
    }
    __syncthreads();

    // ---- epilogue (old mapping): gather Xq/Xk, lrelu, A2 heads, shfl reduce ----
    int tx = tid & 15, ty = tid >> 4;
    float4 c10 = *reinterpret_cast<const float4*>(&g_c1[tx * 4]);
    float4 c11 = *reinterpret_cast<const float4*>(&g_c1[64 + tx * 4]);

    float p[4][8];
    #pragma unroll
    for (int i = 0; i < 4; i++) {
        int el = ty * 4 + i;
        int e = e0 + el;
        int ec = (e < E) ? e : (E - 1);
        int src = EI[ec], tgt = EI[E + ec];
        float4 a0 = *reinterpret_cast<const float4*>(&smem[el * 132 + tx * 4]);
        float4 a1 = *reinterpret_cast<const float4*>(&smem[el * 132 + 64 + tx * 4]);
        float4 q0 = *reinterpret_cast<const float4*>(&g_Q[src * 128 + tx * 4]);
        float4 q1 = *reinterpret_cast<const float4*>(&g_Q[src * 128 + 64 + tx * 4]);
        float4 k0v = *reinterpret_cast<const float4*>(&g_Kf[tgt * 128 + tx * 4]);
        float4 k1v = *reinterpret_cast<const float4*>(&g_Kf[tgt * 128 + 64 + tx * 4]);
        float hm[8];
        hm[0] = lrelu(a0.x + q0.x + k0v.x + c10.x);
        hm[1] = lrelu(a0.y + q0.y + k0v.y + c10.y);
        hm[2] = lrelu(a0.z + q0.z + k0v.z + c10.z);
        hm[3] = lrelu(a0.w + q0.w + k0v.w + c10.w);
        hm[4] = lrelu(a1.x + q1.x + k1v.x + c11.x);
        hm[5] = lrelu(a1.y + q1.y + k1v.y + c11.y);
        hm[6] = lrelu(a1.z + q1.z + k1v.z + c11.z);
        hm[7] = lrelu(a1.w + q1.w + k1v.w + c11.w);
        #pragma unroll
        for (int h = 0; h < 8; h++) {
            float s = 0.f;
            #pragma unroll
            for (int jj = 0; jj < 4; jj++) {
                s += hm[jj]     * smem[OFF_A2 + (tx * 4 + jj) * 8 + h];
                s += hm[4 + jj] * smem[OFF_A2 + (64 + tx * 4 + jj) * 8 + h];
            }
            p[i][h] = s;
        }
    }
    #pragma unroll
    for (int off = 1; off < 16; off <<= 1) {
        #pragma unroll
        for (int i = 0; i < 4; i++)
            #pragma unroll
            for (int h = 0; h < 8; h++)
                p[i][h] += __shfl_xor_sync(0xffffffffu, p[i][h], off);
    }
    if (tx == 0) {
        #pragma unroll
        for (int i = 0; i < 4; i++) {
            int e = e0 + ty * 4 + i;
            if (e < E) {
                float ssum = 0.f;
                #pragma unroll
                for (int h = 0; h < 8; h++) ssum += lrelu(p[i][h] + smem[OFF_B2 + h]);
                g_s[e] = ssum * 0.125f;
            }
        }
    }
}

// ---------------- global softmax over E edges: one pass + combine ----------------
__global__ void __launch_bounds__(256) softmax_part_kernel(int E) {
    float m = -3.4e38f, sum = 0.f;
    for (int i = blockIdx.x * 256 + threadIdx.x; i < E; i += gridDim.x * 256) {
        float v = g_s[i];
        if (v > m) { sum = sum * __expf(m - v) + 1.f; m = v; }
        else       { sum += __expf(v - m); }
    }
    __shared__ float sm[256], su[256];
    sm[threadIdx.x] = m; su[threadIdx.x] = sum;
    __syncthreads();
    for (int off = 128; off; off >>= 1) {
        if (threadIdx.x < off) {
            float m2 = sm[threadIdx.x + off], s2 = su[threadIdx.x + off];
            float mm = fmaxf(sm[threadIdx.x], m2);
            su[threadIdx.x] = su[threadIdx.x] * __expf(sm[threadIdx.x] - mm) + s2 * __expf(m2 - mm);
            sm[threadIdx.x] = mm;
        }
        __syncthreads();
    }
    if (threadIdx.x == 0) { g_pmax[blockIdx.x] = sm[0]; g_psum[blockIdx.x] = su[0]; }
}

__global__ void __launch_bounds__(512) softmax_final_kernel() {
    __shared__ float sm[512], su[512];
    int t = threadIdx.x;
    sm[t] = g_pmax[t]; su[t] = g_psum[t];
    __syncthreads();
    for (int off = 256; off; off >>= 1) {
        if (t < off) {
            float m2 = sm[t + off], s2 = su[t + off];
            float mm = fmaxf(sm[t], m2);
            su[t] = su[t] * __expf(sm[t] - mm) + s2 * __expf(m2 - mm);
            sm[t] = mm;
        }
        __syncthreads();
    }
    if (t == 0) { g_red[0] = sm[0]; g_red[1] = 1.0f / su[0]; }
}

// ---------------- scatter: acc[src] += w[e] * v[tgt] ----------------
__global__ void __launch_bounds__(256) scatter_kernel(const int* __restrict__ EI, int E) {
    int t = blockIdx.x * 256 + threadIdx.x;
    int e = t >> 5;
    if (e >= E) return;
    int lane = t & 31;
    float gmax = g_red[0], ginv = g_red[1];
    float w = __expf(g_s[e] - gmax) * ginv;
    int src = EI[e], tgt = EI[E + e];
    float4 v = *reinterpret_cast<const float4*>(&g_V[tgt * 128 + lane * 4]);
    float* dst = &g_acc[src * 128 + lane * 4];
    asm volatile("red.global.add.v4.f32 [%0], {%1, %2, %3, %4};"
                 :: "l"(dst), "f"(w * v.x), "f"(w * v.y), "f"(w * v.z), "f"(w * v.w)
                 : "memory");
}

// ---------------- zero accumulator ----------------
__global__ void zero_kernel(int count) {
    for (int i = blockIdx.x * 256 + threadIdx.x; i < count; i += gridDim.x * 256)
        g_acc[i] = 0.f;
}

// ---------------- layernorm epilogue ----------------
__global__ void __launch_bounds__(256) ln_kernel(const float* __restrict__ gamma,
                                                 const float* __restrict__ beta,
                                                 float* __restrict__ out, int Nn) {
    int warp = threadIdx.x >> 5, lane = threadIdx.x & 31;
    int n = blockIdx.x * 8 + warp;
    if (n >= Nn) return;
    float4 h = *reinterpret_cast<const float4*>(&g_H[n * 128 + lane * 4]);
    float4 a = *reinterpret_cast<const float4*>(&g_acc[n * 128 + lane * 4]);
    float y[4] = {h.x + a.x, h.y + a.y, h.z + a.z, h.w + a.w};
    float sum = y[0] + y[1] + y[2] + y[3];
    float sq  = y[0] * y[0] + y[1] * y[1] + y[2] * y[2] + y[3] * y[3];
    #pragma unroll
    for (int off = 16; off >= 1; off >>= 1) {
        sum += __shfl_xor_sync(0xffffffffu, sum, off);
        sq  += __shfl_xor_sync(0xffffffffu, sq, off);
    }
    float mu  = sum * (1.f / 128.f);
    float var = sq * (1.f / 128.f) - mu * mu;
    float rs = rsqrtf(var + 1e-5f);
    #pragma unroll
    for (int c = 0; c < 4; c++) {
        int j = lane * 4 + c;
        out[n * 128 + j] = gamma[j] * (y[c] - mu) * rs + beta[j];
    }
}

// ---------------- launch ----------------
extern "C" void kernel_launch(void* const* d_in, const int* in_sizes, int n_in,
                              void* d_out, int out_size) {
    const float* node_features = (const float*)d_in[0];
    const float* edge_features = (const float*)d_in[1];
    const float* Wn = (const float*)d_in[2];
    const float* bn = (const float*)d_in[3];
    const float* Wq = (const float*)d_in[4];
    const float* bq = (const float*)d_in[5];
    const float* Wk = (const float*)d_in[6];
    const float* bk = (const float*)d_in[7];
    const float* Wv = (const float*)d_in[8];
    const float* bv = (const float*)d_in[9];
    const float* We = (const float*)d_in[10];
    const float* be = (const float*)d_in[11];
    const float* A1 = (const float*)d_in[12];
    const float* b1 = (const float*)d_in[13];
    const float* A2 = (const float*)d_in[14];
    const float* b2 = (const float*)d_in[15];
    const float* gamma = (const float*)d_in[16];
    const float* beta  = (const float*)d_in[17];
    const int*   EI    = (const int*)d_in[18];
    float* out = (float*)d_out;

    int Nn = in_sizes[0] / 128;
    int E  = in_sizes[18] / 2;

    cudaFuncSetAttribute(edge_fused_kernel,
                         cudaFuncAttributeMaxDynamicSharedMemorySize, EDGE_SMEM_BYTES);

    zero_kernel<<<2048, 256>>>(Nn * 128);
    prep_kernel<<<(65536 + 8192 + 128 + 512 + 255) / 256, 256>>>(
        Wn, Wq, Wk, Wv, We, A1, b1, bq, bk, be, bn, bv);
    node_gemm_kernel<<<dim3(4, (Nn + 63) / 64), 256>>>(node_features, Nn);
    edge_fused_kernel<<<(E + 63) / 64, 256, EDGE_SMEM_BYTES>>>(edge_features, EI, E, A2, b2);
    softmax_part_kernel<<<512, 256>>>(E);
    softmax_final_kernel<<<1, 512>>>();
    scatter_kernel<<<(E * 32 + 255) / 256, 256>>>(EI, E);
    ln_kernel<<<(Nn + 7) / 8, 256>>>(gamma, beta, out, Nn);
}

// round 7
// speedup vs baseline: 1.0652x; 1.0652x over previous
#include <cuda_runtime.h>
#include <cstdint>

#define NN_MAX 50000
#define EE_MAX 400000

// ---------------- scratch (device globals; no allocs allowed) ----------------
__device__ float g_Wcomb[128 * 512];      // [k][j]: Wn | Wq@A1q | Wk@A1k | Wv
__device__ float g_bc[512];               // bn | 0 | 0 | bv
__device__ float4 g_MeFrag[8 * 16 * 32];  // Me=We@A1e in mma fragment layout (hi0,hi1,lo0,lo1)
__device__ float g_c1[128];               // bq@A1q + bk@A1k + be@A1e + b1
__device__ float g_H[NN_MAX * 128];
__device__ float g_Q[NN_MAX * 128];
__device__ float g_Kf[NN_MAX * 128];
__device__ float g_V[NN_MAX * 128];
__device__ float g_s[EE_MAX];
__device__ float g_pmax[512];
__device__ float g_psum[512];
__device__ float g_red[2];                // gmax, 1/gsum
__device__ float g_acc[NN_MAX * 128];

__device__ __forceinline__ float lrelu(float x) { return x > 0.f ? x : 0.2f * x; }

__device__ __forceinline__ uint32_t f2tf32(float x) {
    uint32_t r; asm("cvt.rna.tf32.f32 %0, %1;" : "=r"(r) : "f"(x)); return r;
}

__device__ __forceinline__ void mma_tf32(float c[4], const uint32_t a[4],
                                         uint32_t b0, uint32_t b1) {
    asm volatile(
        "mma.sync.aligned.m16n8k8.row.col.f32.tf32.tf32.f32 "
        "{%0,%1,%2,%3}, {%4,%5,%6,%7}, {%8,%9}, {%0,%1,%2,%3};"
        : "+f"(c[0]), "+f"(c[1]), "+f"(c[2]), "+f"(c[3])
        : "r"(a[0]), "r"(a[1]), "r"(a[2]), "r"(a[3]), "r"(b0), "r"(b1));
}

// ---------------- prep: fold weights ----------------
// t ranges:
//   [0, 65536)        : g_Wcomb
//   [65536, 69632)    : g_MeFrag (4096 float4 entries)
//   [69632, 69760)    : g_c1
//   [69760, 70272)    : g_bc
__global__ void prep_kernel(const float* __restrict__ Wn, const float* __restrict__ Wq,
                            const float* __restrict__ Wk, const float* __restrict__ Wv,
                            const float* __restrict__ We, const float* __restrict__ A1,
                            const float* __restrict__ b1, const float* __restrict__ bq,
                            const float* __restrict__ bk, const float* __restrict__ be,
                            const float* __restrict__ bn, const float* __restrict__ bv) {
    int t = blockIdx.x * 256 + threadIdx.x;
    if (t < 128 * 512) {
        int k = t >> 9, j = t & 511;
        float val;
        if (j < 128) {
            val = Wn[k * 128 + j];
        } else if (j < 256) {
            int jj = j - 128; float s = 0.f;
            #pragma unroll 8
            for (int u = 0; u < 128; u++) s += Wq[k * 128 + u] * A1[u * 128 + jj];
            val = s;
        } else if (j < 384) {
            int jj = j - 256; float s = 0.f;
            #pragma unroll 8
            for (int u = 0; u < 128; u++) s += Wk[k * 128 + u] * A1[(128 + u) * 128 + jj];
            val = s;
        } else {
            val = Wv[k * 128 + (j - 384)];
        }
        g_Wcomb[t] = val;
    } else if (t < 65536 + 4096) {
        // Me fragment: Me[k][n] = sum_u We[k][u] * A1[(256+u)][n], k<64, n<128
        // entry i -> kt = i>>9, nt = (i>>5)&15, lane = i&31; g=lane>>2, t4=lane&3
        // b0 row k1 = kt*8+t4, b1 row k2 = k1+4, col n = nt*8+g
        int i = t - 65536;
        int kt = i >> 9, nt = (i >> 5) & 15, lane = i & 31;
        int g = lane >> 2, t4 = lane & 3;
        int k1 = kt * 8 + t4, k2 = k1 + 4;
        int n = nt * 8 + g;
        float s1 = 0.f, s2 = 0.f;
        #pragma unroll 8
        for (int u = 0; u < 128; u++) {
            float a = A1[(256 + u) * 128 + n];
            s1 += We[k1 * 128 + u] * a;
            s2 += We[k2 * 128 + u] * a;
        }
        float h1 = __uint_as_float(f2tf32(s1));
        float h2 = __uint_as_float(f2tf32(s2));
        float l1 = __uint_as_float(f2tf32(s1 - h1));
        float l2 = __uint_as_float(f2tf32(s2 - h2));
        g_MeFrag[i] = make_float4(h1, h2, l1, l2);
    } else if (t < 65536 + 4096 + 128) {
        int j = t - (65536 + 4096);
        float s = b1[j];
        for (int u = 0; u < 128; u++) {
            s += bq[u] * A1[u * 128 + j];
            s += bk[u] * A1[(128 + u) * 128 + j];
            s += be[u] * A1[(256 + u) * 128 + j];
        }
        g_c1[j] = s;
    } else if (t < 65536 + 4096 + 128 + 512) {
        int j = t - (65536 + 4096 + 128);
        g_bc[j] = (j < 128) ? bn[j] : (j >= 384 ? bv[j - 384] : 0.f);
    }
}

// ---------------- node GEMM: C[M,512] = A[M,128] @ g_Wcomb + g_bc ----------------
__global__ void __launch_bounds__(256) node_gemm_kernel(const float* __restrict__ A, int M) {
    __shared__ float sA[64 * 36];
    __shared__ float sB[32 * 128];

    int tid = threadIdx.x;
    int tx = tid & 15, ty = tid >> 4;
    int rowBase = blockIdx.y * 64;
    int colBase = blockIdx.x * 128;

    float acc[4][8];
    #pragma unroll
    for (int i = 0; i < 4; i++)
        #pragma unroll
        for (int j = 0; j < 8; j++) acc[i][j] = 0.f;

    #pragma unroll
    for (int k0 = 0; k0 < 128; k0 += 32) {
        #pragma unroll
        for (int i = 0; i < 2; i++) {
            int s = tid + i * 256;
            int r = s >> 3, c4 = s & 7;
            int row = rowBase + r;
            float4 v = make_float4(0.f, 0.f, 0.f, 0.f);
            if (row < M) v = *reinterpret_cast<const float4*>(&A[row * 128 + k0 + c4 * 4]);
            *reinterpret_cast<float4*>(&sA[r * 36 + c4 * 4]) = v;
        }
        #pragma unroll
        for (int i = 0; i < 4; i++) {
            int s = tid + i * 256;
            int r = s >> 5, c4 = s & 31;
            *reinterpret_cast<float4*>(&sB[r * 128 + c4 * 4]) =
                *reinterpret_cast<const float4*>(&g_Wcomb[(k0 + r) * 512 + colBase + c4 * 4]);
        }
        __syncthreads();
        #pragma unroll
        for (int k = 0; k < 32; k++) {
            float a[4];
            #pragma unroll
            for (int i = 0; i < 4; i++) a[i] = sA[(ty * 4 + i) * 36 + k];
            float4 b0 = *reinterpret_cast<const float4*>(&sB[k * 128 + tx * 4]);
            float4 b1 = *reinterpret_cast<const float4*>(&sB[k * 128 + 64 + tx * 4]);
            #pragma unroll
            for (int i = 0; i < 4; i++) {
                acc[i][0] += a[i] * b0.x; acc[i][1] += a[i] * b0.y;
                acc[i][2] += a[i] * b0.z; acc[i][3] += a[i] * b0.w;
                acc[i][4] += a[i] * b1.x; acc[i][5] += a[i] * b1.y;
                acc[i][6] += a[i] * b1.z; acc[i][7] += a[i] * b1.w;
            }
        }
        __syncthreads();
    }

    int grp = colBase >> 7;
    float* C = (grp == 0) ? g_H : (grp == 1) ? g_Q : (grp == 2) ? g_Kf : g_V;
    float4 bias0 = *reinterpret_cast<const float4*>(&g_bc[colBase + tx * 4]);
    float4 bias1 = *reinterpret_cast<const float4*>(&g_bc[colBase + 64 + tx * 4]);
    #pragma unroll
    for (int i = 0; i < 4; i++) {
        int row = rowBase + ty * 4 + i;
        if (row < M) {
            float4 o0 = make_float4(acc[i][0] + bias0.x, acc[i][1] + bias0.y,
                                    acc[i][2] + bias0.z, acc[i][3] + bias0.w);
            float4 o1 = make_float4(acc[i][4] + bias1.x, acc[i][5] + bias1.y,
                                    acc[i][6] + bias1.z, acc[i][7] + bias1.w);
            *reinterpret_cast<float4*>(&C[row * 128 + tx * 4])      = o0;
            *reinterpret_cast<float4*>(&C[row * 128 + 64 + tx * 4]) = o1;
        }
    }
}

// ---------------- fused edge kernel (tf32 mma, precomputed B fragments) ----------------
// per block: 128 edges. Each warp owns 16 edges x all 128 cols (c[16][4]).
// A: EF staged raw in smem, converted hi/lo in registers per kt.
// B: one LDG.128 from g_MeFrag per (kt,nt) -> 3 compensated MMAs.
// C staged through smem, then epilogue: hm = lrelu(c + Q[src] + K[tgt] + c1),
// heads via A2, shfl-reduce -> s[e].
//
// smem (floats): [0,16896) C stage [128][132]  (EF raw [128][68]=8704 lives here first)
//                [16896,17920) A2; [17920,17928) b2
#define ESM_A2  16896
#define ESM_B2  17920
#define ESM_FLOATS 17928
#define ESM_BYTES (ESM_FLOATS * 4)

__global__ void __launch_bounds__(256) edge_fused_kernel(
    const float* __restrict__ EF, const int* __restrict__ EI, int E,
    const float* __restrict__ A2, const float* __restrict__ b2) {
    extern __shared__ float smem[];

    int tid = threadIdx.x;
    int e0 = blockIdx.x * 128;

    for (int i = tid; i < 1024; i += 256) smem[ESM_A2 + i] = A2[i];
    if (tid < 8) smem[ESM_B2 + tid] = b2[tid];

    // stage EF raw: 128 rows x 64 feats, stride 68 (2048 float4, 8 per thread)
    #pragma unroll
    for (int i = 0; i < 8; i++) {
        int s = tid + i * 256;
        int r = s >> 4, c4 = s & 15;
        int e = e0 + r;
        float4 v = make_float4(0.f, 0.f, 0.f, 0.f);
        if (e < E) v = *reinterpret_cast<const float4*>(&EF[e * 64 + c4 * 4]);
        *reinterpret_cast<float4*>(&smem[r * 68 + c4 * 4]) = v;
    }
    __syncthreads();

    int w = tid >> 5, lane = tid & 31;
    int g = lane >> 2, t4 = lane & 3;
    int m0 = w * 16;

    float c[16][4];
    #pragma unroll
    for (int nt = 0; nt < 16; nt++)
        #pragma unroll
        for (int j = 0; j < 4; j++) c[nt][j] = 0.f;

    #pragma unroll 1
    for (int kt = 0; kt < 8; kt++) {
        float af[4];
        af[0] = smem[(m0 + g) * 68 + kt * 8 + t4];
        af[1] = smem[(m0 + g + 8) * 68 + kt * 8 + t4];
        af[2] = smem[(m0 + g) * 68 + kt * 8 + t4 + 4];
        af[3] = smem[(m0 + g + 8) * 68 + kt * 8 + t4 + 4];
        uint32_t ahi[4], alo[4];
        #pragma unroll
        for (int j = 0; j < 4; j++) {
            ahi[j] = f2tf32(af[j]);
            alo[j] = f2tf32(af[j] - __uint_as_float(ahi[j]));
        }
        const float4* bf = &g_MeFrag[(kt * 16) * 32 + lane];
        #pragma unroll
        for (int nt = 0; nt < 16; nt++) {
            float4 f = bf[nt * 32];
            uint32_t bh0 = __float_as_uint(f.x), bh1 = __float_as_uint(f.y);
            uint32_t bl0 = __float_as_uint(f.z), bl1 = __float_as_uint(f.w);
            mma_tf32(c[nt], ahi, bh0, bh1);
            mma_tf32(c[nt], alo, bh0, bh1);
            mma_tf32(c[nt], ahi, bl0, bl1);
        }
    }
    __syncthreads();   // all EF reads done before C overwrites the region

    // stage C: [edge][col], stride 132
    #pragma unroll
    for (int nt = 0; nt < 16; nt++) {
        int col = nt * 8 + t4 * 2;
        *reinterpret_cast<float2*>(&smem[(m0 + g) * 132 + col]) =
            make_float2(c[nt][0], c[nt][1]);
        *reinterpret_cast<float2*>(&smem[(m0 + g + 8) * 132 + col]) =
            make_float2(c[nt][2], c[nt][3]);
    }
    __syncthreads();

    // epilogue: 16 ty-groups x 8 edges each
    int tx = tid & 15, ty = tid >> 4;
    float4 c10 = *reinterpret_cast<const float4*>(&g_c1[tx * 4]);
    float4 c11 = *reinterpret_cast<const float4*>(&g_c1[64 + tx * 4]);

    float p[8][8];
    #pragma unroll
    for (int i = 0; i < 8; i++) {
        int el = ty * 8 + i;
        int e = e0 + el;
        int ec = (e < E) ? e : (E - 1);
        int src = EI[ec], tgt = EI[E + ec];
        float4 a0 = *reinterpret_cast<const float4*>(&smem[el * 132 + tx * 4]);
        float4 a1 = *reinterpret_cast<const float4*>(&smem[el * 132 + 64 + tx * 4]);
        float4 q0 = *reinterpret_cast<const float4*>(&g_Q[src * 128 + tx * 4]);
        float4 q1 = *reinterpret_cast<const float4*>(&g_Q[src * 128 + 64 + tx * 4]);
        float4 k0v = *reinterpret_cast<const float4*>(&g_Kf[tgt * 128 + tx * 4]);
        float4 k1v = *reinterpret_cast<const float4*>(&g_Kf[tgt * 128 + 64 + tx * 4]);
        float hm[8];
        hm[0] = lrelu(a0.x + q0.x + k0v.x + c10.x);
        hm[1] = lrelu(a0.y + q0.y + k0v.y + c10.y);
        hm[2] = lrelu(a0.z + q0.z + k0v.z + c10.z);
        hm[3] = lrelu(a0.w + q0.w + k0v.w + c10.w);
        hm[4] = lrelu(a1.x + q1.x + k1v.x + c11.x);
        hm[5] = lrelu(a1.y + q1.y + k1v.y + c11.y);
        hm[6] = lrelu(a1.z + q1.z + k1v.z + c11.z);
        hm[7] = lrelu(a1.w + q1.w + k1v.w + c11.w);
        #pragma unroll
        for (int h = 0; h < 8; h++) {
            float s = 0.f;
            #pragma unroll
            for (int jj = 0; jj < 4; jj++) {
                s += hm[jj]     * smem[ESM_A2 + (tx * 4 + jj) * 8 + h];
                s += hm[4 + jj] * smem[ESM_A2 + (64 + tx * 4 + jj) * 8 + h];
            }
            p[i][h] = s;
        }
    }
    #pragma unroll
    for (int off = 1; off < 16; off <<= 1) {
        #pragma unroll
        for (int i = 0; i < 8; i++)
            #pragma unroll
            for (int h = 0; h < 8; h++)
                p[i][h] += __shfl_xor_sync(0xffffffffu, p[i][h], off);
    }
    if (tx == 0) {
        #pragma unroll
        for (int i = 0; i < 8; i++) {
            int e = e0 + ty * 8 + i;
            if (e < E) {
                float ssum = 0.f;
                #pragma unroll
                for (int h = 0; h < 8; h++) ssum += lrelu(p[i][h] + smem[ESM_B2 + h]);
                g_s[e] = ssum * 0.125f;
            }
        }
    }
}

// ---------------- global softmax over E edges: one pass + combine ----------------
__global__ void __launch_bounds__(256) softmax_part_kernel(int E) {
    float m = -3.4e38f, sum = 0.f;
    for (int i = blockIdx.x * 256 + threadIdx.x; i < E; i += gridDim.x * 256) {
        float v = g_s[i];
        if (v > m) { sum = sum * __expf(m - v) + 1.f; m = v; }
        else       { sum += __expf(v - m); }
    }
    __shared__ float sm[256], su[256];
    sm[threadIdx.x] = m; su[threadIdx.x] = sum;
    __syncthreads();
    for (int off = 128; off; off >>= 1) {
        if (threadIdx.x < off) {
            float m2 = sm[threadIdx.x + off], s2 = su[threadIdx.x + off];
            float mm = fmaxf(sm[threadIdx.x], m2);
            su[threadIdx.x] = su[threadIdx.x] * __expf(sm[threadIdx.x] - mm) + s2 * __expf(m2 - mm);
            sm[threadIdx.x] = mm;
        }
        __syncthreads();
    }
    if (threadIdx.x == 0) { g_pmax[blockIdx.x] = sm[0]; g_psum[blockIdx.x] = su[0]; }
}

__global__ void __launch_bounds__(512) softmax_final_kernel() {
    __shared__ float sm[512], su[512];
    int t = threadIdx.x;
    sm[t] = g_pmax[t]; su[t] = g_psum[t];
    __syncthreads();
    for (int off = 256; off; off >>= 1) {
        if (t < off) {
            float m2 = sm[t + off], s2 = su[t + off];
            float mm = fmaxf(sm[t], m2);
            su[t] = su[t] * __expf(sm[t] - mm) + s2 * __expf(m2 - mm);
            sm[t] = mm;
        }
        __syncthreads();
    }
    if (t == 0) { g_red[0] = sm[0]; g_red[1] = 1.0f / su[0]; }
}

// ---------------- scatter: acc[src] += w[e] * v[tgt] ----------------
__global__ void __launch_bounds__(256) scatter_kernel(const int* __restrict__ EI, int E) {
    int t = blockIdx.x * 256 + threadIdx.x;
    int e = t >> 5;
    if (e >= E) return;
    int lane = t & 31;
    float gmax = g_red[0], ginv = g_red[1];
    float w = __expf(g_s[e] - gmax) * ginv;
    int src = EI[e], tgt = EI[E + e];
    float4 v = *reinterpret_cast<const float4*>(&g_V[tgt * 128 + lane * 4]);
    float* dst = &g_acc[src * 128 + lane * 4];
    asm volatile("red.global.add.v4.f32 [%0], {%1, %2, %3, %4};"
                 :: "l"(dst), "f"(w * v.x), "f"(w * v.y), "f"(w * v.z), "f"(w * v.w)
                 : "memory");
}

// ---------------- zero accumulator ----------------
__global__ void zero_kernel(int count) {
    for (int i = blockIdx.x * 256 + threadIdx.x; i < count; i += gridDim.x * 256)
        g_acc[i] = 0.f;
}

// ---------------- layernorm epilogue ----------------
__global__ void __launch_bounds__(256) ln_kernel(const float* __restrict__ gamma,
                                                 const float* __restrict__ beta,
                                                 float* __restrict__ out, int Nn) {
    int warp = threadIdx.x >> 5, lane = threadIdx.x & 31;
    int n = blockIdx.x * 8 + warp;
    if (n >= Nn) return;
    float4 h = *reinterpret_cast<const float4*>(&g_H[n * 128 + lane * 4]);
    float4 a = *reinterpret_cast<const float4*>(&g_acc[n * 128 + lane * 4]);
    float y[4] = {h.x + a.x, h.y + a.y, h.z + a.z, h.w + a.w};
    float sum = y[0] + y[1] + y[2] + y[3];
    float sq  = y[0] * y[0] + y[1] * y[1] + y[2] * y[2] + y[3] * y[3];
    #pragma unroll
    for (int off = 16; off >= 1; off >>= 1) {
        sum += __shfl_xor_sync(0xffffffffu, sum, off);
        sq  += __shfl_xor_sync(0xffffffffu, sq, off);
    }
    float mu  = sum * (1.f / 128.f);
    float var = sq * (1.f / 128.f) - mu * mu;
    float rs = rsqrtf(var + 1e-5f);
    #pragma unroll
    for (int c = 0; c < 4; c++) {
        int j = lane * 4 + c;
        out[n * 128 + j] = gamma[j] * (y[c] - mu) * rs + beta[j];
    }
}

// ---------------- launch ----------------
extern "C" void kernel_launch(void* const* d_in, const int* in_sizes, int n_in,
                              void* d_out, int out_size) {
    const float* node_features = (const float*)d_in[0];
    const float* edge_features = (const float*)d_in[1];
    const float* Wn = (const float*)d_in[2];
    const float* bn = (const float*)d_in[3];
    const float* Wq = (const float*)d_in[4];
    const float* bq = (const float*)d_in[5];
    const float* Wk = (const float*)d_in[6];
    const float* bk = (const float*)d_in[7];
    const float* Wv = (const float*)d_in[8];
    const float* bv = (const float*)d_in[9];
    const float* We = (const float*)d_in[10];
    const float* be = (const float*)d_in[11];
    const float* A1 = (const float*)d_in[12];
    const float* b1 = (const float*)d_in[13];
    const float* A2 = (const float*)d_in[14];
    const float* b2 = (const float*)d_in[15];
    const float* gamma = (const float*)d_in[16];
    const float* beta  = (const float*)d_in[17];
    const int*   EI    = (const int*)d_in[18];
    float* out = (float*)d_out;

    int Nn = in_sizes[0] / 128;
    int E  = in_sizes[18] / 2;

    cudaFuncSetAttribute(edge_fused_kernel,
                         cudaFuncAttributeMaxDynamicSharedMemorySize, ESM_BYTES);

    zero_kernel<<<2048, 256>>>(Nn * 128);
    prep_kernel<<<(65536 + 4096 + 128 + 512 + 255) / 256, 256>>>(
        Wn, Wq, Wk, Wv, We, A1, b1, bq, bk, be, bn, bv);
    node_gemm_kernel<<<dim3(4, (Nn + 63) / 64), 256>>>(node_features, Nn);
    edge_fused_kernel<<<(E + 127) / 128, 256, ESM_BYTES>>>(edge_features, EI, E, A2, b2);
    softmax_part_kernel<<<512, 256>>>(E);
    softmax_final_kernel<<<1, 512>>>();
    scatter_kernel<<<(E * 32 + 255) / 256, 256>>>(EI, E);
    ln_kernel<<<(Nn + 7) / 8, 256>>>(gamma, beta, out, Nn);
}